// round 5
// baseline (speedup 1.0000x reference)
#include <cuda_runtime.h>
#include <math.h>

#define IGNORE_LABEL (-100LL)
#define MAXB 64

// zero-initialized at module load; final_kernel re-zeroes after consuming,
// so every launch (and every graph replay) starts from zeroed scratch.
__device__ double g_tasksum[MAXB];
__device__ int    g_correct[MAXB];
__device__ int    g_valid[MAXB];

__device__ __forceinline__ float frcp_fast(float t) {
    float r;
    asm("rcp.approx.ftz.f32 %0, %1;" : "=f"(r) : "f"(t));
    return r;
}

__device__ __forceinline__ float smap(float v) {
    // s(x) = x<0 ? 1/(1-x) : x+1
    float r = frcp_fast(1.0f - v);
    return v < 0.0f ? r : v + 1.0f;
}

// one block per token row
__global__ void __launch_bounds__(256) row_kernel(
        const float* __restrict__ logits,
        const void* __restrict__ labels_raw,
        int V, int Lseq) {
    const int row = blockIdx.x;
    const int tid = threadIdx.x;
    const int nt  = blockDim.x;
    const float* __restrict__ x = logits + (size_t)row * V;

    // ---- labels dtype probe (warp 0; identical result in every block) ----
    // Interpret the first 32 entries as int64: 32*8B = 256B, in-bounds under
    // either dtype (labels buffer is >= rows*4 bytes, rows >= 64).
    __shared__ int s_is64;
    if (tid < 32) {
        long long v = ((const long long*)labels_raw)[tid];
        bool okv = (v >= 0 && v < (long long)V) || v == IGNORE_LABEL;
        unsigned m = __ballot_sync(0xffffffffu, okv);
        if (tid == 0) s_is64 = (m == 0xffffffffu);
    }

    float sumA = 0.f, sumB = 0.f;
    float lmax = -INFINITY;
    int   lidx = 0x7fffffff;

    const int V4 = V >> 2;
    const float4* __restrict__ x4 = (const float4*)x;
    #pragma unroll 4
    for (int i = tid; i < V4; i += nt) {
        float4 v = __ldg(&x4[i]);
        int base = i << 2;
        float s0 = smap(v.x);
        float s1 = smap(v.y);
        float s2 = smap(v.z);
        float s3 = smap(v.w);
        sumA += s0 + s1;
        sumB += s2 + s3;
        // strict > keeps first (smallest) index within a thread,
        // since per-thread visit order is strictly increasing index.
        if (v.x > lmax) { lmax = v.x; lidx = base + 0; }
        if (v.y > lmax) { lmax = v.y; lidx = base + 1; }
        if (v.z > lmax) { lmax = v.z; lidx = base + 2; }
        if (v.w > lmax) { lmax = v.w; lidx = base + 3; }
    }
    // tail (V not multiple of 4)
    for (int i = (V4 << 2) + tid; i < V; i += nt) {
        float v = __ldg(&x[i]);
        sumA += smap(v);
        if (v > lmax) { lmax = v; lidx = i; }
    }

    __shared__ float  ssum[256];
    __shared__ float  smax[256];
    __shared__ int    sidx[256];
    ssum[tid] = sumA + sumB;
    smax[tid] = lmax;
    sidx[tid] = lidx;
    __syncthreads();
    for (int s = nt >> 1; s > 0; s >>= 1) {
        if (tid < s) {
            ssum[tid] += ssum[tid + s];
            float mv = smax[tid + s]; int mi = sidx[tid + s];
            if (mv > smax[tid] || (mv == smax[tid] && mi < sidx[tid])) {
                smax[tid] = mv; sidx[tid] = mi;
            }
        }
        __syncthreads();
    }

    if (tid == 0) {
        long long label;
        if (s_is64) label = ((const long long*)labels_raw)[row];
        else        label = (long long)((const int*)labels_raw)[row];

        if (label >= 0 && label < (long long)V) {
            int b = row / Lseq;
            double xl = (double)x[(int)label];
            double sl = xl < 0.0 ? 1.0 / (1.0 - xl + 1e-30) : xl + 1.0;
            double pt = log((double)ssum[0]) - log(sl);   // -log(s_label/sum)
            atomicAdd(&g_tasksum[b], pt);
            atomicAdd(&g_valid[b], 1);
            if ((long long)sidx[0] == label) atomicAdd(&g_correct[b], 1);
        }
    }
}

__global__ void final_kernel(const float* __restrict__ qh,
                             const float* __restrict__ qc,
                             float* __restrict__ out, int Bn) {
    if (threadIdx.x == 0 && blockIdx.x == 0) {
        float Ltask = 0.f;
        float lh = 0.f, lc = 0.f;
        for (int b = 0; b < Bn; b++) {
            float cnt = (float)(g_valid[b] > 1 ? g_valid[b] : 1);
            Ltask += (float)g_tasksum[b] / cnt;
            float t = (g_correct[b] == g_valid[b]) ? 1.f : 0.f;
            float xh = qh[b];
            lh += fmaxf(xh, 0.f) - xh * t + log1pf(expf(-fabsf(xh)));
            float tc = 1.f / (1.f + expf(-xh));
            float xc = qc[b];
            lc += fmaxf(xc, 0.f) - xc * tc + log1pf(expf(-fabsf(xc)));
            // reset scratch for the next launch / graph replay
            g_tasksum[b] = 0.0;
            g_valid[b]   = 0;
            g_correct[b] = 0;
        }
        Ltask /= (float)Bn;
        float Lhalt = 0.5f * (lh / (float)Bn + lc / (float)Bn);
        out[0] = Ltask + Lhalt;
    }
}

extern "C" void kernel_launch(void* const* d_in, const int* in_sizes, int n_in,
                              void* d_out, int out_size) {
    // Identify inputs by size, not position.
    int li = 0;
    for (int i = 1; i < n_in; i++) if (in_sizes[i] > in_sizes[li]) li = i;
    int lab = -1;
    for (int i = 0; i < n_in; i++) {
        if (i == li) continue;
        if (lab < 0 || in_sizes[i] > in_sizes[lab]) lab = i;
    }
    int qi[2]; int nq = 0;
    for (int i = 0; i < n_in && nq < 2; i++) {
        if (i != li && i != lab) qi[nq++] = i;
    }

    const float* logits = (const float*)d_in[li];
    const void*  labels = d_in[lab];
    const float* qh     = (const float*)d_in[qi[0]];
    const float* qc     = (const float*)d_in[qi[1]];

    const int Bn   = in_sizes[qi[0]];
    const int rows = in_sizes[lab];
    const int Lseq = rows / Bn;
    const int V    = (int)((long long)in_sizes[li] / rows);

    row_kernel<<<rows, 256>>>(logits, labels, V, Lseq);
    final_kernel<<<1, 32>>>(qh, qc, (float*)d_out, Bn);
}

// round 7
// speedup vs baseline: 1.2217x; 1.2217x over previous
#include <cuda_runtime.h>
#include <math.h>

#define IGNORE_LABEL (-100LL)
#define MAXB 64

// zero at module load; the finalizing block resets everything after use,
// so each launch / graph replay starts from zeroed scratch.
__device__ double g_tasksum[MAXB];
__device__ int    g_correct[MAXB];
__device__ int    g_valid[MAXB];
__device__ int    g_labels_is64;
__device__ unsigned int g_done;

__device__ __forceinline__ float frcp_fast(float t) {
    float r;
    asm("rcp.approx.ftz.f32 %0, %1;" : "=f"(r) : "f"(t));
    return r;
}

__device__ __forceinline__ float smap(float v) {
    // s(x) = x<0 ? 1/(1-x) : x+1
    float r = frcp_fast(1.0f - v);
    return v < 0.0f ? r : v + 1.0f;
}

// tiny: decide whether labels buffer is int64 or int32.
// Reads first 32 entries as int64 (256B, in-bounds under either dtype).
// Random labels make a false int64-detection probability ~(1/32000)^16 ~ 0.
__global__ void probe_kernel(const void* __restrict__ labels, int V) {
    long long v = ((const long long*)labels)[threadIdx.x];
    bool okv = (v >= 0 && v < (long long)V) || v == IGNORE_LABEL;
    unsigned m = __ballot_sync(0xffffffffu, okv);
    if (threadIdx.x == 0) g_labels_is64 = (m == 0xffffffffu);
}

// one block per token row; the last block to finish also computes the final loss.
__global__ void __launch_bounds__(256) row_kernel(
        const float* __restrict__ logits,
        const void* __restrict__ labels_raw,
        const float* __restrict__ qh,
        const float* __restrict__ qc,
        float* __restrict__ out,
        int V, int Lseq, int Bn) {
    const int row = blockIdx.x;
    const int tid = threadIdx.x;
    const int nt  = blockDim.x;
    const float* __restrict__ x = logits + (size_t)row * V;

    float sumA = 0.f, sumB = 0.f;
    float lmax = -INFINITY;
    int   lidx = 0x7fffffff;

    const int V4 = V >> 2;
    const float4* __restrict__ x4 = (const float4*)x;
    #pragma unroll 4
    for (int i = tid; i < V4; i += nt) {
        float4 v = __ldg(&x4[i]);
        int base = i << 2;
        float s0 = smap(v.x);
        float s1 = smap(v.y);
        float s2 = smap(v.z);
        float s3 = smap(v.w);
        sumA += s0 + s1;
        sumB += s2 + s3;
        // strict > keeps first (smallest) index within a thread,
        // since per-thread visit order is strictly increasing index.
        if (v.x > lmax) { lmax = v.x; lidx = base + 0; }
        if (v.y > lmax) { lmax = v.y; lidx = base + 1; }
        if (v.z > lmax) { lmax = v.z; lidx = base + 2; }
        if (v.w > lmax) { lmax = v.w; lidx = base + 3; }
    }
    // tail (V not multiple of 4)
    for (int i = (V4 << 2) + tid; i < V; i += nt) {
        float v = __ldg(&x[i]);
        sumA += smap(v);
        if (v > lmax) { lmax = v; lidx = i; }
    }

    __shared__ float  ssum[256];
    __shared__ float  smax[256];
    __shared__ int    sidx[256];
    ssum[tid] = sumA + sumB;
    smax[tid] = lmax;
    sidx[tid] = lidx;
    __syncthreads();
    for (int s = nt >> 1; s > 0; s >>= 1) {
        if (tid < s) {
            ssum[tid] += ssum[tid + s];
            float mv = smax[tid + s]; int mi = sidx[tid + s];
            if (mv > smax[tid] || (mv == smax[tid] && mi < sidx[tid])) {
                smax[tid] = mv; sidx[tid] = mi;
            }
        }
        __syncthreads();
    }

    if (tid == 0) {
        long long label;
        if (g_labels_is64) label = ((const long long*)labels_raw)[row];
        else               label = (long long)((const int*)labels_raw)[row];

        if (label >= 0 && label < (long long)V) {
            int b = row / Lseq;
            double xl = (double)x[(int)label];
            double sl = xl < 0.0 ? 1.0 / (1.0 - xl + 1e-30) : xl + 1.0;
            double pt = log((double)ssum[0]) - log(sl);   // -log(s_label/sum)
            atomicAdd(&g_tasksum[b], pt);
            atomicAdd(&g_valid[b], 1);
            if ((long long)sidx[0] == label) atomicAdd(&g_correct[b], 1);
        }

        // ---- last-block finalize ----
        __threadfence();
        unsigned int ticket = atomicAdd(&g_done, 1u);
        if (ticket == gridDim.x - 1) {
            // all other blocks' atomics are globally visible now
            volatile double* vsum = g_tasksum;
            volatile int*    vval = g_valid;
            volatile int*    vcor = g_correct;
            float Ltask = 0.f, lh = 0.f, lc = 0.f;
            for (int b = 0; b < Bn; b++) {
                int    nv = vval[b];
                int    nc = vcor[b];
                double ts = vsum[b];
                float cnt = (float)(nv > 1 ? nv : 1);
                Ltask += (float)ts / cnt;
                float t = (nc == nv) ? 1.f : 0.f;
                float xh = qh[b];
                lh += fmaxf(xh, 0.f) - xh * t + log1pf(expf(-fabsf(xh)));
                float tc = 1.f / (1.f + expf(-xh));
                float xc = qc[b];
                lc += fmaxf(xc, 0.f) - xc * tc + log1pf(expf(-fabsf(xc)));
                // reset scratch for the next launch / graph replay
                vsum[b] = 0.0;
                vval[b] = 0;
                vcor[b] = 0;
            }
            Ltask /= (float)Bn;
            float Lhalt = 0.5f * (lh / (float)Bn + lc / (float)Bn);
            out[0] = Ltask + Lhalt;
            __threadfence();
            g_done = 0;
        }
    }
}

extern "C" void kernel_launch(void* const* d_in, const int* in_sizes, int n_in,
                              void* d_out, int out_size) {
    // Identify inputs by size, not position.
    int li = 0;
    for (int i = 1; i < n_in; i++) if (in_sizes[i] > in_sizes[li]) li = i;
    int lab = -1;
    for (int i = 0; i < n_in; i++) {
        if (i == li) continue;
        if (lab < 0 || in_sizes[i] > in_sizes[lab]) lab = i;
    }
    int qi[2]; int nq = 0;
    for (int i = 0; i < n_in && nq < 2; i++) {
        if (i != li && i != lab) qi[nq++] = i;
    }

    const float* logits = (const float*)d_in[li];
    const void*  labels = d_in[lab];
    const float* qh     = (const float*)d_in[qi[0]];
    const float* qc     = (const float*)d_in[qi[1]];

    const int Bn   = in_sizes[qi[0]];
    const int rows = in_sizes[lab];
    const int Lseq = rows / Bn;
    const int V    = (int)((long long)in_sizes[li] / rows);

    probe_kernel<<<1, 32>>>(labels, V);
    row_kernel<<<rows, 256>>>(logits, labels, qh, qc, (float*)d_out, V, Lseq, Bn);
}

// round 8
// speedup vs baseline: 1.2327x; 1.0090x over previous
#include <cuda_runtime.h>
#include <math.h>

#define IGNORE_LABEL (-100LL)
#define MAXB 64

// zero at module load; the finalizing block resets everything after use,
// so each launch / graph replay starts from zeroed scratch.
__device__ double g_tasksum[MAXB];
__device__ int    g_correct[MAXB];
__device__ int    g_valid[MAXB];
__device__ int    g_labels_is64;
__device__ unsigned int g_done;

__device__ __forceinline__ float frcp_fast(float t) {
    float r;
    asm("rcp.approx.ftz.f32 %0, %1;" : "=f"(r) : "f"(t));
    return r;
}

__device__ __forceinline__ float smap(float v) {
    // s(x) = x<0 ? 1/(1-x) : x+1
    float r = frcp_fast(1.0f - v);
    return v < 0.0f ? r : v + 1.0f;
}

// tiny: decide whether labels buffer is int64 or int32.
// Reads first 32 entries as int64 (256B, in-bounds under either dtype).
__global__ void probe_kernel(const void* __restrict__ labels, int V) {
    long long v = ((const long long*)labels)[threadIdx.x];
    bool okv = (v >= 0 && v < (long long)V) || v == IGNORE_LABEL;
    unsigned m = __ballot_sync(0xffffffffu, okv);
    if (threadIdx.x == 0) g_labels_is64 = (m == 0xffffffffu);
}

// one block per token row; the last block to finish also computes the final loss.
__global__ void __launch_bounds__(256) row_kernel(
        const float* __restrict__ logits,
        const void* __restrict__ labels_raw,
        const float* __restrict__ qh,
        const float* __restrict__ qc,
        float* __restrict__ out,
        int V, int Lseq, int Bn) {
    const int row = blockIdx.x;
    const int tid = threadIdx.x;
    const int nt  = blockDim.x;
    const float* __restrict__ x = logits + (size_t)row * V;

    __shared__ float     ssum[256];
    __shared__ float     smaxv[256];
    __shared__ int       sidx[256];
    __shared__ float     sh_xl;
    __shared__ long long sh_label;
    __shared__ int       sh_need_scan;

    if (tid == 0) {
        long long label;
        if (g_labels_is64) label = ((const long long*)labels_raw)[row];
        else               label = (long long)((const int*)labels_raw)[row];
        sh_label = label;
        int safe = (label >= 0 && label < (long long)V) ? (int)label : 0;
        sh_xl = x[safe];
        sh_need_scan = 0;
    }
    __syncthreads();
    const float xl = sh_xl;

    float sumA = 0.f, sumB = 0.f;
    float vmax = -INFINITY;

    const int V4 = V >> 2;
    const float4* __restrict__ x4 = (const float4*)x;
    #pragma unroll 4
    for (int i = tid; i < V4; i += nt) {
        float4 v = __ldg(&x4[i]);
        sumA += smap(v.x) + smap(v.y);
        sumB += smap(v.z) + smap(v.w);
        vmax = fmaxf(vmax, fmaxf(fmaxf(v.x, v.y), fmaxf(v.z, v.w)));
    }
    for (int i = (V4 << 2) + tid; i < V; i += nt) {
        float v = __ldg(&x[i]);
        sumA += smap(v);
        vmax = fmaxf(vmax, v);
    }

    ssum[tid]  = sumA + sumB;
    smaxv[tid] = vmax;
    __syncthreads();
    for (int s = nt >> 1; s > 0; s >>= 1) {
        if (tid < s) {
            ssum[tid]  += ssum[tid + s];
            smaxv[tid]  = fmaxf(smaxv[tid], smaxv[tid + s]);
        }
        __syncthreads();
    }

    // rare path: label attains the row max -> need exact first-index argmax
    if (tid == 0) {
        long long label = sh_label;
        if (label >= 0 && label < (long long)V && xl == smaxv[0])
            sh_need_scan = 1;
    }
    __syncthreads();

    int arg_idx = -1;
    if (sh_need_scan) {
        // block-parallel exact argmax with first-index tie-break (second pass)
        float lmax = -INFINITY;
        int   lidx = 0x7fffffff;
        for (int i = tid; i < V4; i += nt) {
            float4 v = __ldg(&x4[i]);
            int base = i << 2;
            if (v.x > lmax) { lmax = v.x; lidx = base + 0; }
            if (v.y > lmax) { lmax = v.y; lidx = base + 1; }
            if (v.z > lmax) { lmax = v.z; lidx = base + 2; }
            if (v.w > lmax) { lmax = v.w; lidx = base + 3; }
        }
        for (int i = (V4 << 2) + tid; i < V; i += nt) {
            float v = __ldg(&x[i]);
            if (v > lmax) { lmax = v; lidx = i; }
        }
        smaxv[tid] = lmax;   // safe: sum tree already consumed; ssum[0] untouched
        sidx[tid]  = lidx;
        __syncthreads();
        for (int s = nt >> 1; s > 0; s >>= 1) {
            if (tid < s) {
                float mv = smaxv[tid + s]; int mi = sidx[tid + s];
                if (mv > smaxv[tid] || (mv == smaxv[tid] && mi < sidx[tid])) {
                    smaxv[tid] = mv; sidx[tid] = mi;
                }
            }
            __syncthreads();
        }
        arg_idx = sidx[0];
    }

    if (tid == 0) {
        long long label = sh_label;
        if (label >= 0 && label < (long long)V) {
            int b = row / Lseq;
            double xd = (double)xl;
            double sl = xd < 0.0 ? 1.0 / (1.0 - xd + 1e-30) : xd + 1.0;
            double pt = log((double)ssum[0]) - log(sl);   // -log(s_label/sum)
            atomicAdd(&g_tasksum[b], pt);
            atomicAdd(&g_valid[b], 1);
            bool correct = sh_need_scan && ((long long)arg_idx == label);
            if (correct) atomicAdd(&g_correct[b], 1);
        }

        // ---- last-block finalize ----
        __threadfence();
        unsigned int ticket = atomicAdd(&g_done, 1u);
        if (ticket == gridDim.x - 1) {
            volatile double* vsum = g_tasksum;
            volatile int*    vval = g_valid;
            volatile int*    vcor = g_correct;
            float Ltask = 0.f, lh = 0.f, lc = 0.f;
            for (int b = 0; b < Bn; b++) {
                int    nv = vval[b];
                int    nc = vcor[b];
                double ts = vsum[b];
                float cnt = (float)(nv > 1 ? nv : 1);
                Ltask += (float)ts / cnt;
                float t = (nc == nv) ? 1.f : 0.f;
                float xh = qh[b];
                lh += fmaxf(xh, 0.f) - xh * t + log1pf(expf(-fabsf(xh)));
                float tc = 1.f / (1.f + expf(-xh));
                float xc = qc[b];
                lc += fmaxf(xc, 0.f) - xc * tc + log1pf(expf(-fabsf(xc)));
                vsum[b] = 0.0;
                vval[b] = 0;
                vcor[b] = 0;
            }
            Ltask /= (float)Bn;
            float Lhalt = 0.5f * (lh / (float)Bn + lc / (float)Bn);
            out[0] = Ltask + Lhalt;
            __threadfence();
            g_done = 0;
        }
    }
}

extern "C" void kernel_launch(void* const* d_in, const int* in_sizes, int n_in,
                              void* d_out, int out_size) {
    // Identify inputs by size, not position.
    int li = 0;
    for (int i = 1; i < n_in; i++) if (in_sizes[i] > in_sizes[li]) li = i;
    int lab = -1;
    for (int i = 0; i < n_in; i++) {
        if (i == li) continue;
        if (lab < 0 || in_sizes[i] > in_sizes[lab]) lab = i;
    }
    int qi[2]; int nq = 0;
    for (int i = 0; i < n_in && nq < 2; i++) {
        if (i != li && i != lab) qi[nq++] = i;
    }

    const float* logits = (const float*)d_in[li];
    const void*  labels = d_in[lab];
    const float* qh     = (const float*)d_in[qi[0]];
    const float* qc     = (const float*)d_in[qi[1]];

    const int Bn   = in_sizes[qi[0]];
    const int rows = in_sizes[lab];
    const int Lseq = rows / Bn;
    const int V    = (int)((long long)in_sizes[li] / rows);

    probe_kernel<<<1, 32>>>(labels, V);
    row_kernel<<<rows, 256>>>(logits, labels, qh, qc, (float*)d_out, V, Lseq, Bn);
}